// round 9
// baseline (speedup 1.0000x reference)
#include <cuda_runtime.h>
#include <cstdint>

#define NN 100000
#define EE 1600000
#define GG 64
#define SCAN_B 391   // ceil(NN/256)

typedef unsigned long long u64;

// ---------------- scratch (static device memory; no allocs) ----------------
__device__ __align__(16) float g_bufA[NN * 64];
__device__ __align__(16) float g_bufB[NN * 64];
__device__ __align__(16) float g_bufC[NN * 64];
__device__ int      g_cnt[NN];
__device__ int      g_scan[NN];
__device__ int      g_bsum[SCAN_B];
__device__ int      g_boff[SCAN_B];
__device__ int      g_done;
__device__ int      g_rowptr[NN + 1];
__device__ int      g_cursor[NN];
__device__ __align__(8) int2 g_csr[EE];   // (col, w-bits)
__device__ float    g_dis[NN];
__device__ double   g_sum[192];           // 3 layers x 64
__device__ double   g_sumsq[192];
__device__ __align__(8) float g_scale[64];
__device__ __align__(8) float g_shift[64];
__device__ unsigned g_pooled[GG * 64];

// ---------------- helpers ----------------
__device__ __forceinline__ unsigned enc_f32(float f) {
    unsigned u = __float_as_uint(f);
    return (u & 0x80000000u) ? ~u : (u | 0x80000000u);
}
__device__ __forceinline__ float dec_f32(unsigned u) {
    return (u & 0x80000000u) ? __uint_as_float(u & 0x7FFFFFFFu) : __uint_as_float(~u);
}
__device__ __forceinline__ u64 splat2(float f) {
    u64 r;
    unsigned u = __float_as_uint(f);
    asm("mov.b64 %0, {%1,%2};" : "=l"(r) : "r"(u), "r"(u));
    return r;
}
#define FMA2(acc, a, w) asm("fma.rn.f32x2 %0, %1, %2, %0;" : "+l"(acc) : "l"(a), "l"(w))
__device__ __forceinline__ void unpack2(u64 v, float& lo, float& hi) {
    unsigned a, b;
    asm("mov.b64 {%0,%1}, %2;" : "=r"(a), "=r"(b) : "l"(v));
    lo = __uint_as_float(a);
    hi = __uint_as_float(b);
}
__device__ __forceinline__ float lrelu(float v) { return v > 0.f ? v : 0.01f * v; }

// ---------------- degree histogram (int) ----------------
__global__ void k_deg(const int* __restrict__ ei) {
    int e = blockIdx.x * blockDim.x + threadIdx.x;
    if (e < EE) atomicAdd(&g_cnt[ei[e]], 1);
}

// ---------------- scan phase 1+2 fused (last block scans block sums) ----------------
__global__ void k_scan12() {
    __shared__ int sh[256];
    __shared__ int lastFlag;
    int t = threadIdx.x, i = blockIdx.x * 256 + t;
    int v = (i < NN) ? g_cnt[i] : 0;
    if (i < NN) g_dis[i] = v > 0 ? rsqrtf((float)v) : 0.0f;
    sh[t] = v;
    __syncthreads();
    for (int o = 1; o < 256; o <<= 1) {
        int x = (t >= o) ? sh[t - o] : 0;
        __syncthreads();
        sh[t] += x;
        __syncthreads();
    }
    if (i < NN) g_scan[i] = sh[t];
    if (t == 255) g_bsum[blockIdx.x] = sh[255];

    if (t == 0) {
        __threadfence();
        int old = atomicAdd(&g_done, 1);
        lastFlag = (old == SCAN_B - 1);
    }
    __syncthreads();
    if (lastFlag && t < 32) {
        __threadfence();
        int lane = t;
        int run = 0;
        for (int c = 0; c < SCAN_B; c += 32) {
            int idx = c + lane;
            int x = (idx < SCAN_B) ? g_bsum[idx] : 0;
            int s = x;
#pragma unroll
            for (int o = 1; o < 32; o <<= 1) {
                int y = __shfl_up_sync(0xffffffffu, s, o);
                if (lane >= o) s += y;
            }
            if (idx < SCAN_B) g_boff[idx] = run + s - x;  // exclusive
            run += __shfl_sync(0xffffffffu, s, 31);
        }
        if (lane == 0) g_done = 0;   // self-reset for graph replay
    }
}

__global__ void k_scan3() {
    int i = blockIdx.x * blockDim.x + threadIdx.x;
    if (i < NN) {
        int rp = g_scan[i] - g_cnt[i] + g_boff[i >> 8];
        g_rowptr[i] = rp;
        g_cursor[i] = rp;
    }
    if (i == 0) g_rowptr[NN] = EE;
}

// ---------------- CSR fill (norm folded in) ----------------
__global__ void k_fill(const int* __restrict__ ei) {
    int e = blockIdx.x * blockDim.x + threadIdx.x;
    if (e >= EE) return;
    int r = ei[e], c = ei[EE + e];
    float w = -g_dis[r] * g_dis[c];
    int pos = atomicAdd(&g_cursor[r], 1);
    g_csr[pos] = make_int2(c, __float_as_int(w));
}

// ---------------- CSR SpMM: warp/row; lane-parallel CSR load + shfl broadcast ----------------
// ACT: apply BN scale/shift + leaky-ReLU to gathered src values on the fly.
template <bool ACT>
__global__ __launch_bounds__(256) void k_spmm_csr(const float2* __restrict__ src,
                                                  float2* __restrict__ dst) {
    int row = blockIdx.x * 8 + (threadIdx.x >> 5);
    if (row >= NN) return;
    int lane = threadIdx.x & 31;
    int p0 = g_rowptr[row], pe = g_rowptr[row + 1];
    float2 sc, sh;
    if (ACT) {
        sc = ((const float2*)g_scale)[lane];
        sh = ((const float2*)g_shift)[lane];
    }
    float2 acc = make_float2(0.f, 0.f);
    for (int base = p0; base < pe; base += 32) {
        int idx = base + lane;
        int2 e = make_int2(0, 0);
        if (idx < pe) e = g_csr[idx];            // coalesced: one LDG.64/lane
        int cnt = min(32, pe - base);
#pragma unroll 4
        for (int k = 0; k < cnt; k++) {
            int c   = __shfl_sync(0xffffffffu, e.x, k);
            float w = __int_as_float(__shfl_sync(0xffffffffu, e.y, k));
            float2 v = src[(size_t)c * 32 + lane];
            if (ACT) {
                v.x = lrelu(fmaf(v.x, sc.x, sh.x));
                v.y = lrelu(fmaf(v.y, sc.y, sh.y));
            }
            acc.x += w * v.x;
            acc.y += w * v.y;
        }
    }
    dst[(size_t)row * 32 + lane] = acc;
}

// ---------------- fused 3-matrix GEMM (f32x2) + BN-stats epilogue ----------------
// out = Z@(W0-W2) + T@W1 + P@(2*W2) + b. ACT: apply BN+lrelu to Z on load.
template <bool ACT>
__global__ __launch_bounds__(512, 1) void k_gemm3(const float* __restrict__ Z,
                                                  const float* __restrict__ T,
                                                  const float* __restrict__ P,
                                                  const float* __restrict__ W,
                                                  const float* __restrict__ bias,
                                                  float* __restrict__ out, int loff) {
    extern __shared__ float sm[];
    float* Wd = sm;                 // 192*128 floats (splatted pairs)
    float* At = sm + 192 * 128;     // 192*128 floats

    int tid = threadIdx.x;
    int base = blockIdx.x * 128;

    for (int i = tid; i < 192 * 64; i += 512) {
        int kk = i >> 6, c = i & 63;
        int m = kk >> 6, kr = kk & 63;
        float w = W[m * 4096 + kr * 64 + c];
        if (m == 0) w -= W[8192 + kr * 64 + c];
        else if (m == 2) w *= 2.0f;
        float2* d = (float2*)(Wd + (size_t)kk * 128 + c * 2);
        *d = make_float2(w, w);
    }
    const float4* srcs[3] = {(const float4*)Z, (const float4*)T, (const float4*)P};
#pragma unroll
    for (int m = 0; m < 3; m++) {
        const float4* s = srcs[m];
        for (int i = tid; i < 128 * 16; i += 512) {
            int row = i & 127, c4 = i >> 7;
            float4 v = make_float4(0.f, 0.f, 0.f, 0.f);
            if (base + row < NN) v = s[(size_t)(base + row) * 16 + c4];
            if (ACT && m == 0) {
                float4 sc4 = ((const float4*)g_scale)[c4];
                float4 sh4 = ((const float4*)g_shift)[c4];
                v.x = lrelu(fmaf(v.x, sc4.x, sh4.x));
                v.y = lrelu(fmaf(v.y, sc4.y, sh4.y));
                v.z = lrelu(fmaf(v.z, sc4.z, sh4.z));
                v.w = lrelu(fmaf(v.w, sc4.w, sh4.w));
            }
            float* d = At + (size_t)(m * 64 + c4 * 4) * 128 + row;
            d[0] = v.x; d[128] = v.y; d[256] = v.z; d[384] = v.w;
        }
    }
    __syncthreads();

    int warp = tid >> 5, lane = tid & 31;
    int j0 = warp * 4;

    u64 acc[2][4];
#pragma unroll
    for (int c = 0; c < 4; c++) {
        u64 b = splat2(bias[j0 + c]);
        acc[0][c] = b;
        acc[1][c] = b;
    }

    const char* wb = (const char*)(Wd + j0 * 2);     // + kk*512B
    const char* ab = (const char*)(At + 2 * lane);   // + kk*512B

#pragma unroll 4
    for (int kk = 0; kk < 192; kk++) {
        ulonglong2 w01 = *(const ulonglong2*)(wb + (size_t)kk * 512);
        ulonglong2 w23 = *(const ulonglong2*)(wb + (size_t)kk * 512 + 16);
        u64 a0 = *(const u64*)(ab + (size_t)kk * 512);
        u64 a1 = *(const u64*)(ab + (size_t)kk * 512 + 256);
        FMA2(acc[0][0], a0, w01.x); FMA2(acc[0][1], a0, w01.y);
        FMA2(acc[0][2], a0, w23.x); FMA2(acc[0][3], a0, w23.y);
        FMA2(acc[1][0], a1, w01.x); FMA2(acc[1][1], a1, w01.y);
        FMA2(acc[1][2], a1, w23.x); FMA2(acc[1][3], a1, w23.y);
    }

    float s[4] = {0.f, 0.f, 0.f, 0.f}, q[4] = {0.f, 0.f, 0.f, 0.f};
#pragma unroll
    for (int rp = 0; rp < 2; rp++) {
        int re = base + rp * 64 + 2 * lane;
        float lo[4], hi[4];
#pragma unroll
        for (int c = 0; c < 4; c++) unpack2(acc[rp][c], lo[c], hi[c]);
        if (re < NN) {
            *(float4*)(out + (size_t)re * 64 + j0) = make_float4(lo[0], lo[1], lo[2], lo[3]);
#pragma unroll
            for (int c = 0; c < 4; c++) { s[c] += lo[c]; q[c] += lo[c] * lo[c]; }
        }
        if (re + 1 < NN) {
            *(float4*)(out + (size_t)(re + 1) * 64 + j0) = make_float4(hi[0], hi[1], hi[2], hi[3]);
#pragma unroll
            for (int c = 0; c < 4; c++) { s[c] += hi[c]; q[c] += hi[c] * hi[c]; }
        }
    }
#pragma unroll
    for (int o = 16; o > 0; o >>= 1) {
#pragma unroll
        for (int c = 0; c < 4; c++) {
            s[c] += __shfl_down_sync(0xffffffffu, s[c], o);
            q[c] += __shfl_down_sync(0xffffffffu, q[c], o);
        }
    }
    if (lane == 0) {
#pragma unroll
        for (int c = 0; c < 4; c++) {
            atomicAdd(&g_sum[loff + j0 + c], (double)s[c]);
            atomicAdd(&g_sumsq[loff + j0 + c], (double)q[c]);
        }
    }
}

// ---------------- shortcut GEMM (f32x2): out = X @ Wsc + bsc ----------------
__global__ __launch_bounds__(512, 2) void k_sc2(const float* __restrict__ X,
                                                const float* __restrict__ W,
                                                const float* __restrict__ bias,
                                                float* __restrict__ out) {
    extern __shared__ float sm[];
    float* Wd = sm;               // 64*128
    float* At = sm + 64 * 128;    // 64*128

    int tid = threadIdx.x;
    int base = blockIdx.x * 128;

    for (int i = tid; i < 64 * 64; i += 512) {
        int kk = i >> 6, c = i & 63;
        float w = W[kk * 64 + c];
        float2* d = (float2*)(Wd + (size_t)kk * 128 + c * 2);
        *d = make_float2(w, w);
    }
    for (int i = tid; i < 128 * 16; i += 512) {
        int row = i & 127, c4 = i >> 7;
        float4 v = make_float4(0.f, 0.f, 0.f, 0.f);
        if (base + row < NN) v = ((const float4*)X)[(size_t)(base + row) * 16 + c4];
        float* d = At + (size_t)(c4 * 4) * 128 + row;
        d[0] = v.x; d[128] = v.y; d[256] = v.z; d[384] = v.w;
    }
    __syncthreads();

    int warp = tid >> 5, lane = tid & 31;
    int j0 = warp * 4;

    u64 acc[2][4];
#pragma unroll
    for (int c = 0; c < 4; c++) {
        u64 b = splat2(bias[j0 + c]);
        acc[0][c] = b;
        acc[1][c] = b;
    }
    const char* wb = (const char*)(Wd + j0 * 2);
    const char* ab = (const char*)(At + 2 * lane);
#pragma unroll 4
    for (int kk = 0; kk < 64; kk++) {
        ulonglong2 w01 = *(const ulonglong2*)(wb + (size_t)kk * 512);
        ulonglong2 w23 = *(const ulonglong2*)(wb + (size_t)kk * 512 + 16);
        u64 a0 = *(const u64*)(ab + (size_t)kk * 512);
        u64 a1 = *(const u64*)(ab + (size_t)kk * 512 + 256);
        FMA2(acc[0][0], a0, w01.x); FMA2(acc[0][1], a0, w01.y);
        FMA2(acc[0][2], a0, w23.x); FMA2(acc[0][3], a0, w23.y);
        FMA2(acc[1][0], a1, w01.x); FMA2(acc[1][1], a1, w01.y);
        FMA2(acc[1][2], a1, w23.x); FMA2(acc[1][3], a1, w23.y);
    }
#pragma unroll
    for (int rp = 0; rp < 2; rp++) {
        int re = base + rp * 64 + 2 * lane;
        float lo[4], hi[4];
#pragma unroll
        for (int c = 0; c < 4; c++) unpack2(acc[rp][c], lo[c], hi[c]);
        if (re < NN)
            *(float4*)(out + (size_t)re * 64 + j0) = make_float4(lo[0], lo[1], lo[2], lo[3]);
        if (re + 1 < NN)
            *(float4*)(out + (size_t)(re + 1) * 64 + j0) = make_float4(hi[0], hi[1], hi[2], hi[3]);
    }
}

__global__ void k_finalize(const float* __restrict__ g, const float* __restrict__ be, int loff) {
    int j = threadIdx.x;
    double mu = g_sum[loff + j] / (double)NN;
    double var = g_sumsq[loff + j] / (double)NN - mu * mu;
    float sc = g[j] * (float)(1.0 / sqrt(var + 1e-5));
    g_scale[j] = sc;
    g_shift[j] = be[j] - (float)mu * sc;
}

// ---------------- layer 3: BN apply + lrelu + shortcut + segment-max pool ----------------
__global__ void k_apply3(const float* __restrict__ pre, const float* __restrict__ sc,
                         const int* __restrict__ batch) {
    int i = blockIdx.x * blockDim.x + threadIdx.x;
    if (i >= NN * 64) return;
    int j = i & 63, row = i >> 6;
    float v = pre[i] * g_scale[j] + g_shift[j];
    v = v > 0.f ? v : 0.01f * v;
    v += sc[i];
    atomicMax(&g_pooled[batch[row] * 64 + j], enc_f32(v));
}

// ---------------- final: pooled @ w_lin + b_lin ----------------
__global__ void k_final(const float* __restrict__ wlin, const float* __restrict__ blin,
                        float* __restrict__ out) {
    int g = blockIdx.x, j = threadIdx.x;
    float v = dec_f32(g_pooled[g * 64 + j]) * wlin[j];
#pragma unroll
    for (int o = 16; o > 0; o >>= 1) v += __shfl_down_sync(0xffffffffu, v, o);
    __shared__ float s2[2];
    if ((j & 31) == 0) s2[j >> 5] = v;
    __syncthreads();
    if (j == 0) out[g] = s2[0] + s2[1] + blin[0];
}

// ---------------- launcher ----------------
extern "C" void kernel_launch(void* const* d_in, const int* in_sizes, int n_in,
                              void* d_out, int out_size) {
    const float* x     = (const float*)d_in[0];
    const int*   ei    = (const int*)d_in[1];
    const int*   batch = (const int*)d_in[2];
    const float* W[3]  = {(const float*)d_in[3], (const float*)d_in[5], (const float*)d_in[7]};
    const float* B[3]  = {(const float*)d_in[4], (const float*)d_in[6], (const float*)d_in[8]};
    const float* Ga[3] = {(const float*)d_in[9], (const float*)d_in[11], (const float*)d_in[13]};
    const float* Be[3] = {(const float*)d_in[10], (const float*)d_in[12], (const float*)d_in[14]};
    const float* wsc  = (const float*)d_in[15];
    const float* bsc  = (const float*)d_in[16];
    const float* wlin = (const float*)d_in[17];
    const float* blin = (const float*)d_in[18];
    float* out = (float*)d_out;

    const int GEMM_SMEM = 2 * 192 * 128 * 4;   // 196608 B
    const int SC_SMEM   = 2 * 64 * 128 * 4;    // 65536 B
    cudaFuncSetAttribute(k_gemm3<false>, cudaFuncAttributeMaxDynamicSharedMemorySize, GEMM_SMEM);
    cudaFuncSetAttribute(k_gemm3<true>,  cudaFuncAttributeMaxDynamicSharedMemorySize, GEMM_SMEM);
    cudaFuncSetAttribute(k_sc2, cudaFuncAttributeMaxDynamicSharedMemorySize, SC_SMEM);

    void *pA, *pB, *pC, *pcnt, *psum, *psumsq, *ppool;
    cudaGetSymbolAddress(&pA, g_bufA);
    cudaGetSymbolAddress(&pB, g_bufB);
    cudaGetSymbolAddress(&pC, g_bufC);
    cudaGetSymbolAddress(&pcnt, g_cnt);
    cudaGetSymbolAddress(&psum, g_sum);
    cudaGetSymbolAddress(&psumsq, g_sumsq);
    cudaGetSymbolAddress(&ppool, g_pooled);

    float* bufA = (float*)pA;
    float* bufB = (float*)pB;
    float* bufC = (float*)pC;

    const int EB = (EE + 255) / 256;
    const int NB = (NN + 255) / 256;
    const int FB = (NN * 64 + 255) / 256;
    const int RB = (NN + 127) / 128;           // gemm3/sc2 grid
    const int SPB = (NN + 7) / 8;              // spmm grid

    // ---- CSR build ----
    cudaMemsetAsync(pcnt, 0, NN * sizeof(int));
    k_deg<<<EB, 256>>>(ei);
    k_scan12<<<SCAN_B, 256>>>();
    k_scan3<<<NB, 256>>>();
    k_fill<<<EB, 256>>>(ei);

    cudaMemsetAsync(psum, 0, 192 * sizeof(double));
    cudaMemsetAsync(psumsq, 0, 192 * sizeof(double));

    // ---- layer 1 (no activation on input) ----
    k_spmm_csr<false><<<SPB, 256>>>((const float2*)x, (float2*)bufA);
    k_spmm_csr<false><<<SPB, 256>>>((const float2*)bufA, (float2*)bufB);
    k_gemm3<false><<<RB, 512, GEMM_SMEM>>>(x, bufA, bufB, W[0], B[0], bufC, 0);
    k_finalize<<<1, 64>>>(Ga[0], Be[0], 0);

    // ---- layers 2,3 (activation fused into gather / Z-load) ----
    for (int l = 1; l < 3; l++) {
        k_spmm_csr<true><<<SPB, 256>>>((const float2*)bufC, (float2*)bufA);
        k_spmm_csr<false><<<SPB, 256>>>((const float2*)bufA, (float2*)bufB);
        k_gemm3<true><<<RB, 512, GEMM_SMEM>>>(bufC, bufA, bufB, W[l], B[l], bufC, l * 64);
        k_finalize<<<1, 64>>>(Ga[l], Be[l], l * 64);
    }

    k_sc2<<<RB, 512, SC_SMEM>>>(x, wsc, bsc, bufA);
    cudaMemsetAsync(ppool, 0, GG * 64 * sizeof(unsigned));
    k_apply3<<<FB, 256>>>(bufC, bufA, batch);
    k_final<<<GG, 64>>>(wlin, blin, out);
}

// round 10
// speedup vs baseline: 1.0326x; 1.0326x over previous
#include <cuda_runtime.h>
#include <cstdint>

#define NN 100000
#define EE 1600000
#define GG 64
#define SCAN_B 391   // ceil(NN/256)

typedef unsigned long long u64;

// ---------------- scratch (static device memory; no allocs) ----------------
__device__ __align__(16) float g_bufA[NN * 64];
__device__ __align__(16) float g_bufB[NN * 64];
__device__ __align__(16) float g_bufC[NN * 64];
__device__ int      g_cnt[NN];
__device__ int      g_scan[NN];
__device__ int      g_bsum[SCAN_B];
__device__ int      g_boff[SCAN_B];
__device__ int      g_done;
__device__ int      g_rowptr[NN + 1];
__device__ int      g_cursor[NN];
__device__ __align__(8) int2 g_csr[EE];   // (col, w-bits)
__device__ float    g_dis[NN];
__device__ double   g_sum[192];           // 3 layers x 64
__device__ double   g_sumsq[192];
__device__ unsigned g_pooled[GG * 64];

// ---------------- helpers ----------------
__device__ __forceinline__ unsigned enc_f32(float f) {
    unsigned u = __float_as_uint(f);
    return (u & 0x80000000u) ? ~u : (u | 0x80000000u);
}
__device__ __forceinline__ float dec_f32(unsigned u) {
    return (u & 0x80000000u) ? __uint_as_float(u & 0x7FFFFFFFu) : __uint_as_float(~u);
}
__device__ __forceinline__ u64 splat2(float f) {
    u64 r;
    unsigned u = __float_as_uint(f);
    asm("mov.b64 %0, {%1,%2};" : "=l"(r) : "r"(u), "r"(u));
    return r;
}
#define FMA2(acc, a, w) asm("fma.rn.f32x2 %0, %1, %2, %0;" : "+l"(acc) : "l"(a), "l"(w))
__device__ __forceinline__ void unpack2(u64 v, float& lo, float& hi) {
    unsigned a, b;
    asm("mov.b64 {%0,%1}, %2;" : "=r"(a), "=r"(b) : "l"(v));
    lo = __uint_as_float(a);
    hi = __uint_as_float(b);
}
__device__ __forceinline__ float lrelu(float v) { return v > 0.f ? v : 0.01f * v; }

// compute BN scale/shift for layer offset loff into smem (callers sync after)
__device__ __forceinline__ void bn_params(int tid, int loff,
                                          const float* __restrict__ ga,
                                          const float* __restrict__ be,
                                          float* s_sc, float* s_sh) {
    if (tid < 64) {
        double mu = g_sum[loff + tid] / (double)NN;
        double var = g_sumsq[loff + tid] / (double)NN - mu * mu;
        float sc = ga[tid] * (float)(1.0 / sqrt(var + 1e-5));
        s_sc[tid] = sc;
        s_sh[tid] = be[tid] - (float)mu * sc;
    }
}

// ---------------- degree histogram (int) ----------------
__global__ void k_deg(const int* __restrict__ ei) {
    int e = blockIdx.x * blockDim.x + threadIdx.x;
    if (e < EE) atomicAdd(&g_cnt[ei[e]], 1);
}

// ---------------- scan phase 1+2 fused (last block scans block sums) ----------------
__global__ void k_scan12() {
    __shared__ int sh[256];
    __shared__ int lastFlag;
    int t = threadIdx.x, i = blockIdx.x * 256 + t;
    int v = (i < NN) ? g_cnt[i] : 0;
    if (i < NN) g_dis[i] = v > 0 ? rsqrtf((float)v) : 0.0f;
    sh[t] = v;
    __syncthreads();
    for (int o = 1; o < 256; o <<= 1) {
        int x = (t >= o) ? sh[t - o] : 0;
        __syncthreads();
        sh[t] += x;
        __syncthreads();
    }
    if (i < NN) g_scan[i] = sh[t];
    if (t == 255) g_bsum[blockIdx.x] = sh[255];

    if (t == 0) {
        __threadfence();
        int old = atomicAdd(&g_done, 1);
        lastFlag = (old == SCAN_B - 1);
    }
    __syncthreads();
    if (lastFlag && t < 32) {
        __threadfence();
        int lane = t;
        int run = 0;
        for (int c = 0; c < SCAN_B; c += 32) {
            int idx = c + lane;
            int x = (idx < SCAN_B) ? g_bsum[idx] : 0;
            int s = x;
#pragma unroll
            for (int o = 1; o < 32; o <<= 1) {
                int y = __shfl_up_sync(0xffffffffu, s, o);
                if (lane >= o) s += y;
            }
            if (idx < SCAN_B) g_boff[idx] = run + s - x;  // exclusive
            run += __shfl_sync(0xffffffffu, s, 31);
        }
        if (lane == 0) g_done = 0;   // self-reset for graph replay
    }
}

__global__ void k_scan3() {
    int i = blockIdx.x * blockDim.x + threadIdx.x;
    if (i < NN) {
        int rp = g_scan[i] - g_cnt[i] + g_boff[i >> 8];
        g_rowptr[i] = rp;
        g_cursor[i] = rp;
    }
    if (i == 0) g_rowptr[NN] = EE;
}

// ---------------- CSR fill (norm folded in) ----------------
__global__ void k_fill(const int* __restrict__ ei) {
    int e = blockIdx.x * blockDim.x + threadIdx.x;
    if (e >= EE) return;
    int r = ei[e], c = ei[EE + e];
    float w = -g_dis[r] * g_dis[c];
    int pos = atomicAdd(&g_cursor[r], 1);
    g_csr[pos] = make_int2(c, __float_as_int(w));
}

// ---------------- CSR SpMM: one warp per row, float2 per lane, unroll 4 ----------------
// ACT: apply BN (computed inline from g_sum) + leaky-ReLU to gathered src values.
template <bool ACT>
__global__ __launch_bounds__(256) void k_spmm_csr(const float2* __restrict__ src,
                                                  float2* __restrict__ dst,
                                                  int loff,
                                                  const float* __restrict__ ga,
                                                  const float* __restrict__ be) {
    __shared__ float s_sc[64], s_sh[64];
    if (ACT) {
        bn_params(threadIdx.x, loff, ga, be, s_sc, s_sh);
        __syncthreads();
    }
    int row = blockIdx.x * 8 + (threadIdx.x >> 5);
    if (row >= NN) return;
    int lane = threadIdx.x & 31;
    float2 sc, sh;
    if (ACT) {
        sc = ((const float2*)s_sc)[lane];
        sh = ((const float2*)s_sh)[lane];
    }
    int p = g_rowptr[row], pe = g_rowptr[row + 1];
    float2 acc = make_float2(0.f, 0.f);
    for (; p + 4 <= pe; p += 4) {
        int2 e0 = g_csr[p];
        int2 e1 = g_csr[p + 1];
        int2 e2 = g_csr[p + 2];
        int2 e3 = g_csr[p + 3];
        float2 v0 = src[(size_t)e0.x * 32 + lane];
        float2 v1 = src[(size_t)e1.x * 32 + lane];
        float2 v2 = src[(size_t)e2.x * 32 + lane];
        float2 v3 = src[(size_t)e3.x * 32 + lane];
        if (ACT) {
            v0.x = lrelu(fmaf(v0.x, sc.x, sh.x)); v0.y = lrelu(fmaf(v0.y, sc.y, sh.y));
            v1.x = lrelu(fmaf(v1.x, sc.x, sh.x)); v1.y = lrelu(fmaf(v1.y, sc.y, sh.y));
            v2.x = lrelu(fmaf(v2.x, sc.x, sh.x)); v2.y = lrelu(fmaf(v2.y, sc.y, sh.y));
            v3.x = lrelu(fmaf(v3.x, sc.x, sh.x)); v3.y = lrelu(fmaf(v3.y, sc.y, sh.y));
        }
        float w0 = __int_as_float(e0.y), w1 = __int_as_float(e1.y);
        float w2 = __int_as_float(e2.y), w3 = __int_as_float(e3.y);
        acc.x += w0 * v0.x; acc.y += w0 * v0.y;
        acc.x += w1 * v1.x; acc.y += w1 * v1.y;
        acc.x += w2 * v2.x; acc.y += w2 * v2.y;
        acc.x += w3 * v3.x; acc.y += w3 * v3.y;
    }
    for (; p < pe; p++) {
        int2 a = g_csr[p];
        float2 v = src[(size_t)a.x * 32 + lane];
        if (ACT) {
            v.x = lrelu(fmaf(v.x, sc.x, sh.x));
            v.y = lrelu(fmaf(v.y, sc.y, sh.y));
        }
        float w = __int_as_float(a.y);
        acc.x += w * v.x; acc.y += w * v.y;
    }
    dst[(size_t)row * 32 + lane] = acc;
}

// ---------------- fused 3-matrix GEMM (f32x2) + BN-stats epilogue ----------------
// out = Z@(W0-W2) + T@W1 + P@(2*W2) + b. ACT: apply BN+lrelu to Z on load.
template <bool ACT>
__global__ __launch_bounds__(512, 1) void k_gemm3(const float* __restrict__ Z,
                                                  const float* __restrict__ T,
                                                  const float* __restrict__ P,
                                                  const float* __restrict__ W,
                                                  const float* __restrict__ bias,
                                                  float* __restrict__ out, int loff,
                                                  const float* __restrict__ ga,
                                                  const float* __restrict__ be) {
    extern __shared__ float sm[];
    float* Wd = sm;                 // 192*128 floats (splatted pairs)
    float* At = sm + 192 * 128;     // 192*128 floats
    __shared__ float s_sc[64], s_sh[64];

    int tid = threadIdx.x;
    int base = blockIdx.x * 128;

    if (ACT) bn_params(tid, loff - 64, ga, be, s_sc, s_sh);   // previous layer's stats

    for (int i = tid; i < 192 * 64; i += 512) {
        int kk = i >> 6, c = i & 63;
        int m = kk >> 6, kr = kk & 63;
        float w = W[m * 4096 + kr * 64 + c];
        if (m == 0) w -= W[8192 + kr * 64 + c];
        else if (m == 2) w *= 2.0f;
        float2* d = (float2*)(Wd + (size_t)kk * 128 + c * 2);
        *d = make_float2(w, w);
    }
    if (ACT) __syncthreads();   // s_sc/s_sh ready before Z-tile load
    const float4* srcs[3] = {(const float4*)Z, (const float4*)T, (const float4*)P};
#pragma unroll
    for (int m = 0; m < 3; m++) {
        const float4* s = srcs[m];
        for (int i = tid; i < 128 * 16; i += 512) {
            int row = i & 127, c4 = i >> 7;
            float4 v = make_float4(0.f, 0.f, 0.f, 0.f);
            if (base + row < NN) v = s[(size_t)(base + row) * 16 + c4];
            if (ACT && m == 0) {
                float4 sc4 = ((const float4*)s_sc)[c4];
                float4 sh4 = ((const float4*)s_sh)[c4];
                v.x = lrelu(fmaf(v.x, sc4.x, sh4.x));
                v.y = lrelu(fmaf(v.y, sc4.y, sh4.y));
                v.z = lrelu(fmaf(v.z, sc4.z, sh4.z));
                v.w = lrelu(fmaf(v.w, sc4.w, sh4.w));
            }
            float* d = At + (size_t)(m * 64 + c4 * 4) * 128 + row;
            d[0] = v.x; d[128] = v.y; d[256] = v.z; d[384] = v.w;
        }
    }
    __syncthreads();

    int warp = tid >> 5, lane = tid & 31;
    int j0 = warp * 4;

    u64 acc[2][4];
#pragma unroll
    for (int c = 0; c < 4; c++) {
        u64 b = splat2(bias[j0 + c]);
        acc[0][c] = b;
        acc[1][c] = b;
    }

    const char* wb = (const char*)(Wd + j0 * 2);     // + kk*512B
    const char* ab = (const char*)(At + 2 * lane);   // + kk*512B

#pragma unroll 4
    for (int kk = 0; kk < 192; kk++) {
        ulonglong2 w01 = *(const ulonglong2*)(wb + (size_t)kk * 512);
        ulonglong2 w23 = *(const ulonglong2*)(wb + (size_t)kk * 512 + 16);
        u64 a0 = *(const u64*)(ab + (size_t)kk * 512);
        u64 a1 = *(const u64*)(ab + (size_t)kk * 512 + 256);
        FMA2(acc[0][0], a0, w01.x); FMA2(acc[0][1], a0, w01.y);
        FMA2(acc[0][2], a0, w23.x); FMA2(acc[0][3], a0, w23.y);
        FMA2(acc[1][0], a1, w01.x); FMA2(acc[1][1], a1, w01.y);
        FMA2(acc[1][2], a1, w23.x); FMA2(acc[1][3], a1, w23.y);
    }

    float s[4] = {0.f, 0.f, 0.f, 0.f}, q[4] = {0.f, 0.f, 0.f, 0.f};
#pragma unroll
    for (int rp = 0; rp < 2; rp++) {
        int re = base + rp * 64 + 2 * lane;
        float lo[4], hi[4];
#pragma unroll
        for (int c = 0; c < 4; c++) unpack2(acc[rp][c], lo[c], hi[c]);
        if (re < NN) {
            *(float4*)(out + (size_t)re * 64 + j0) = make_float4(lo[0], lo[1], lo[2], lo[3]);
#pragma unroll
            for (int c = 0; c < 4; c++) { s[c] += lo[c]; q[c] += lo[c] * lo[c]; }
        }
        if (re + 1 < NN) {
            *(float4*)(out + (size_t)(re + 1) * 64 + j0) = make_float4(hi[0], hi[1], hi[2], hi[3]);
#pragma unroll
            for (int c = 0; c < 4; c++) { s[c] += hi[c]; q[c] += hi[c] * hi[c]; }
        }
    }
#pragma unroll
    for (int o = 16; o > 0; o >>= 1) {
#pragma unroll
        for (int c = 0; c < 4; c++) {
            s[c] += __shfl_down_sync(0xffffffffu, s[c], o);
            q[c] += __shfl_down_sync(0xffffffffu, q[c], o);
        }
    }
    if (lane == 0) {
#pragma unroll
        for (int c = 0; c < 4; c++) {
            atomicAdd(&g_sum[loff + j0 + c], (double)s[c]);
            atomicAdd(&g_sumsq[loff + j0 + c], (double)q[c]);
        }
    }
}

// ---------------- shortcut GEMM (f32x2): out = X @ Wsc + bsc ----------------
__global__ __launch_bounds__(512, 2) void k_sc2(const float* __restrict__ X,
                                                const float* __restrict__ W,
                                                const float* __restrict__ bias,
                                                float* __restrict__ out) {
    extern __shared__ float sm[];
    float* Wd = sm;               // 64*128
    float* At = sm + 64 * 128;    // 64*128

    int tid = threadIdx.x;
    int base = blockIdx.x * 128;

    for (int i = tid; i < 64 * 64; i += 512) {
        int kk = i >> 6, c = i & 63;
        float w = W[kk * 64 + c];
        float2* d = (float2*)(Wd + (size_t)kk * 128 + c * 2);
        *d = make_float2(w, w);
    }
    for (int i = tid; i < 128 * 16; i += 512) {
        int row = i & 127, c4 = i >> 7;
        float4 v = make_float4(0.f, 0.f, 0.f, 0.f);
        if (base + row < NN) v = ((const float4*)X)[(size_t)(base + row) * 16 + c4];
        float* d = At + (size_t)(c4 * 4) * 128 + row;
        d[0] = v.x; d[128] = v.y; d[256] = v.z; d[384] = v.w;
    }
    __syncthreads();

    int warp = tid >> 5, lane = tid & 31;
    int j0 = warp * 4;

    u64 acc[2][4];
#pragma unroll
    for (int c = 0; c < 4; c++) {
        u64 b = splat2(bias[j0 + c]);
        acc[0][c] = b;
        acc[1][c] = b;
    }
    const char* wb = (const char*)(Wd + j0 * 2);
    const char* ab = (const char*)(At + 2 * lane);
#pragma unroll 4
    for (int kk = 0; kk < 64; kk++) {
        ulonglong2 w01 = *(const ulonglong2*)(wb + (size_t)kk * 512);
        ulonglong2 w23 = *(const ulonglong2*)(wb + (size_t)kk * 512 + 16);
        u64 a0 = *(const u64*)(ab + (size_t)kk * 512);
        u64 a1 = *(const u64*)(ab + (size_t)kk * 512 + 256);
        FMA2(acc[0][0], a0, w01.x); FMA2(acc[0][1], a0, w01.y);
        FMA2(acc[0][2], a0, w23.x); FMA2(acc[0][3], a0, w23.y);
        FMA2(acc[1][0], a1, w01.x); FMA2(acc[1][1], a1, w01.y);
        FMA2(acc[1][2], a1, w23.x); FMA2(acc[1][3], a1, w23.y);
    }
#pragma unroll
    for (int rp = 0; rp < 2; rp++) {
        int re = base + rp * 64 + 2 * lane;
        float lo[4], hi[4];
#pragma unroll
        for (int c = 0; c < 4; c++) unpack2(acc[rp][c], lo[c], hi[c]);
        if (re < NN)
            *(float4*)(out + (size_t)re * 64 + j0) = make_float4(lo[0], lo[1], lo[2], lo[3]);
        if (re + 1 < NN)
            *(float4*)(out + (size_t)(re + 1) * 64 + j0) = make_float4(hi[0], hi[1], hi[2], hi[3]);
    }
}

// ---------------- layer 3: BN (inline) + lrelu + shortcut + segment-max pool ----------------
// batch is sorted: each thread scans 8 consecutive rows of one feature and flushes
// one atomic per (group,feature) run instead of one per row.
__global__ __launch_bounds__(256) void k_apply3(const float* __restrict__ pre,
                                                const float* __restrict__ sc,
                                                const int* __restrict__ batch,
                                                const float* __restrict__ ga,
                                                const float* __restrict__ be) {
    __shared__ float s_sc[64], s_sh[64];
    bn_params(threadIdx.x, 128, ga, be, s_sc, s_sh);
    __syncthreads();
    int j = threadIdx.x & 63, rg = threadIdx.x >> 6;
    int r0 = blockIdx.x * 32 + rg * 8;
    float scv = s_sc[j], shv = s_sh[j];
    float m = 0.f;
    int curb = -1;
    for (int k = 0; k < 8; k++) {
        int row = r0 + k;
        if (row >= NN) break;
        int b = batch[row];
        float v = lrelu(fmaf(pre[(size_t)row * 64 + j], scv, shv)) + sc[(size_t)row * 64 + j];
        if (b != curb) {
            if (curb >= 0) atomicMax(&g_pooled[curb * 64 + j], enc_f32(m));
            curb = b;
            m = v;
        } else {
            m = fmaxf(m, v);
        }
    }
    if (curb >= 0) atomicMax(&g_pooled[curb * 64 + j], enc_f32(m));
}

// ---------------- final: pooled @ w_lin + b_lin ----------------
__global__ void k_final(const float* __restrict__ wlin, const float* __restrict__ blin,
                        float* __restrict__ out) {
    int g = blockIdx.x, j = threadIdx.x;
    float v = dec_f32(g_pooled[g * 64 + j]) * wlin[j];
#pragma unroll
    for (int o = 16; o > 0; o >>= 1) v += __shfl_down_sync(0xffffffffu, v, o);
    __shared__ float s2[2];
    if ((j & 31) == 0) s2[j >> 5] = v;
    __syncthreads();
    if (j == 0) out[g] = s2[0] + s2[1] + blin[0];
}

// ---------------- launcher ----------------
extern "C" void kernel_launch(void* const* d_in, const int* in_sizes, int n_in,
                              void* d_out, int out_size) {
    const float* x     = (const float*)d_in[0];
    const int*   ei    = (const int*)d_in[1];
    const int*   batch = (const int*)d_in[2];
    const float* W[3]  = {(const float*)d_in[3], (const float*)d_in[5], (const float*)d_in[7]};
    const float* B[3]  = {(const float*)d_in[4], (const float*)d_in[6], (const float*)d_in[8]};
    const float* Ga[3] = {(const float*)d_in[9], (const float*)d_in[11], (const float*)d_in[13]};
    const float* Be[3] = {(const float*)d_in[10], (const float*)d_in[12], (const float*)d_in[14]};
    const float* wsc  = (const float*)d_in[15];
    const float* bsc  = (const float*)d_in[16];
    const float* wlin = (const float*)d_in[17];
    const float* blin = (const float*)d_in[18];
    float* out = (float*)d_out;

    const int GEMM_SMEM = 2 * 192 * 128 * 4;   // 196608 B
    const int SC_SMEM   = 2 * 64 * 128 * 4;    // 65536 B
    cudaFuncSetAttribute(k_gemm3<false>, cudaFuncAttributeMaxDynamicSharedMemorySize, GEMM_SMEM);
    cudaFuncSetAttribute(k_gemm3<true>,  cudaFuncAttributeMaxDynamicSharedMemorySize, GEMM_SMEM);
    cudaFuncSetAttribute(k_sc2, cudaFuncAttributeMaxDynamicSharedMemorySize, SC_SMEM);

    void *pA, *pB, *pC, *pcnt, *psum, *psumsq, *ppool;
    cudaGetSymbolAddress(&pA, g_bufA);
    cudaGetSymbolAddress(&pB, g_bufB);
    cudaGetSymbolAddress(&pC, g_bufC);
    cudaGetSymbolAddress(&pcnt, g_cnt);
    cudaGetSymbolAddress(&psum, g_sum);
    cudaGetSymbolAddress(&psumsq, g_sumsq);
    cudaGetSymbolAddress(&ppool, g_pooled);

    float* bufA = (float*)pA;
    float* bufB = (float*)pB;
    float* bufC = (float*)pC;

    const int EB = (EE + 255) / 256;
    const int NB = (NN + 255) / 256;
    const int RB = (NN + 127) / 128;           // gemm3/sc2 grid
    const int SPB = (NN + 7) / 8;              // spmm grid
    const int AB = (NN + 31) / 32;             // apply3 grid

    // ---- zero accumulators up front ----
    cudaMemsetAsync(psum, 0, 192 * sizeof(double));
    cudaMemsetAsync(psumsq, 0, 192 * sizeof(double));
    cudaMemsetAsync(ppool, 0, GG * 64 * sizeof(unsigned));
    cudaMemsetAsync(pcnt, 0, NN * sizeof(int));

    // ---- CSR build ----
    k_deg<<<EB, 256>>>(ei);
    k_scan12<<<SCAN_B, 256>>>();
    k_scan3<<<NB, 256>>>();
    k_fill<<<EB, 256>>>(ei);

    // ---- layer 1 (no activation on input) ----
    k_spmm_csr<false><<<SPB, 256>>>((const float2*)x, (float2*)bufA, 0, nullptr, nullptr);
    k_spmm_csr<false><<<SPB, 256>>>((const float2*)bufA, (float2*)bufB, 0, nullptr, nullptr);
    k_gemm3<false><<<RB, 512, GEMM_SMEM>>>(x, bufA, bufB, W[0], B[0], bufC, 0, nullptr, nullptr);

    // ---- layers 2,3 (BN+lrelu fused into gather / Z-load, params inline from stats) ----
    for (int l = 1; l < 3; l++) {
        k_spmm_csr<true><<<SPB, 256>>>((const float2*)bufC, (float2*)bufA,
                                       (l - 1) * 64, Ga[l - 1], Be[l - 1]);
        k_spmm_csr<false><<<SPB, 256>>>((const float2*)bufA, (float2*)bufB, 0, nullptr, nullptr);
        k_gemm3<true><<<RB, 512, GEMM_SMEM>>>(bufC, bufA, bufB, W[l], B[l], bufC,
                                              l * 64, Ga[l - 1], Be[l - 1]);
    }

    k_sc2<<<RB, 512, SC_SMEM>>>(x, wsc, bsc, bufA);
    k_apply3<<<AB, 256>>>(bufC, bufA, batch, Ga[2], Be[2]);
    k_final<<<GG, 64>>>(wlin, blin, out);
}

// round 15
// speedup vs baseline: 1.0642x; 1.0306x over previous
#include <cuda_runtime.h>
#include <cstdint>

#define NN 100000
#define EE 1600000
#define GG 64
#define SCAN_B 391   // ceil(NN/256)

typedef unsigned long long u64;

// ---------------- scratch (static device memory; no allocs) ----------------
__device__ __align__(16) float g_bufA[NN * 64];
__device__ __align__(16) float g_bufB[NN * 64];
__device__ __align__(16) float g_bufC[NN * 64];
__device__ int      g_cnt[NN];
__device__ int      g_scan[NN];
__device__ int      g_bsum[SCAN_B];
__device__ int      g_boff[SCAN_B];
__device__ int      g_done;
__device__ int      g_rowptr[NN + 1];
__device__ int      g_cursor[NN];
__device__ __align__(8) int2 g_csr[EE];   // (col, w-bits)
__device__ float    g_dis[NN];
__device__ double   g_sum[192];           // 3 layers x 64
__device__ double   g_sumsq[192];
__device__ unsigned g_pooled[GG * 64];

// ---------------- helpers ----------------
__device__ __forceinline__ unsigned enc_f32(float f) {
    unsigned u = __float_as_uint(f);
    return (u & 0x80000000u) ? ~u : (u | 0x80000000u);
}
__device__ __forceinline__ float dec_f32(unsigned u) {
    return (u & 0x80000000u) ? __uint_as_float(u & 0x7FFFFFFFu) : __uint_as_float(~u);
}
__device__ __forceinline__ u64 splat2(float f) {
    u64 r;
    unsigned u = __float_as_uint(f);
    asm("mov.b64 %0, {%1,%2};" : "=l"(r) : "r"(u), "r"(u));
    return r;
}
#define FMA2(acc, a, w) asm("fma.rn.f32x2 %0, %1, %2, %0;" : "+l"(acc) : "l"(a), "l"(w))
__device__ __forceinline__ void unpack2(u64 v, float& lo, float& hi) {
    unsigned a, b;
    asm("mov.b64 {%0,%1}, %2;" : "=r"(a), "=r"(b) : "l"(v));
    lo = __uint_as_float(a);
    hi = __uint_as_float(b);
}
__device__ __forceinline__ float lrelu(float v) { return v > 0.f ? v : 0.01f * v; }

// compute BN scale/shift for layer offset loff into smem (callers sync after)
__device__ __forceinline__ void bn_params(int tid, int loff,
                                          const float* __restrict__ ga,
                                          const float* __restrict__ be,
                                          float* s_sc, float* s_sh) {
    if (tid < 64) {
        double mu = g_sum[loff + tid] / (double)NN;
        double var = g_sumsq[loff + tid] / (double)NN - mu * mu;
        float sc = ga[tid] * (float)(1.0 / sqrt(var + 1e-5));
        s_sc[tid] = sc;
        s_sh[tid] = be[tid] - (float)mu * sc;
    }
}

// ---------------- degree histogram (int) ----------------
__global__ void k_deg(const int* __restrict__ ei) {
    int e = blockIdx.x * blockDim.x + threadIdx.x;
    if (e < EE) atomicAdd(&g_cnt[ei[e]], 1);
}

// ---------------- scan phase 1+2 fused (last block scans block sums) ----------------
__global__ void k_scan12() {
    __shared__ int sh[256];
    __shared__ int lastFlag;
    int t = threadIdx.x, i = blockIdx.x * 256 + t;
    int v = (i < NN) ? g_cnt[i] : 0;
    if (i < NN) g_dis[i] = v > 0 ? rsqrtf((float)v) : 0.0f;
    sh[t] = v;
    __syncthreads();
    for (int o = 1; o < 256; o <<= 1) {
        int x = (t >= o) ? sh[t - o] : 0;
        __syncthreads();
        sh[t] += x;
        __syncthreads();
    }
    if (i < NN) g_scan[i] = sh[t];
    if (t == 255) g_bsum[blockIdx.x] = sh[255];

    if (t == 0) {
        __threadfence();
        int old = atomicAdd(&g_done, 1);
        lastFlag = (old == SCAN_B - 1);
    }
    __syncthreads();
    if (lastFlag && t < 32) {
        __threadfence();
        int lane = t;
        int run = 0;
        for (int c = 0; c < SCAN_B; c += 32) {
            int idx = c + lane;
            int x = (idx < SCAN_B) ? g_bsum[idx] : 0;
            int s = x;
#pragma unroll
            for (int o = 1; o < 32; o <<= 1) {
                int y = __shfl_up_sync(0xffffffffu, s, o);
                if (lane >= o) s += y;
            }
            if (idx < SCAN_B) g_boff[idx] = run + s - x;  // exclusive
            run += __shfl_sync(0xffffffffu, s, 31);
        }
        if (lane == 0) g_done = 0;   // self-reset for graph replay
    }
}

__global__ void k_scan3() {
    int i = blockIdx.x * blockDim.x + threadIdx.x;
    if (i < NN) {
        int rp = g_scan[i] - g_cnt[i] + g_boff[i >> 8];
        g_rowptr[i] = rp;
        g_cursor[i] = rp;
    }
    if (i == 0) g_rowptr[NN] = EE;
}

// ---------------- CSR fill (norm folded in) ----------------
__global__ void k_fill(const int* __restrict__ ei) {
    int e = blockIdx.x * blockDim.x + threadIdx.x;
    if (e >= EE) return;
    int r = ei[e], c = ei[EE + e];
    float w = -g_dis[r] * g_dis[c];
    int pos = atomicAdd(&g_cursor[r], 1);
    g_csr[pos] = make_int2(c, __float_as_int(w));
}

// ---------------- CSR SpMM: 2 rows per warp (16 lanes x float4 each), unroll 4 ----------------
// Both half-warps run a shared (max) trip count with predicated loads -> no divergence,
// 8 independent gathers in flight per warp.
// ACT: apply BN (computed inline from g_sum) + leaky-ReLU to gathered src values.
template <bool ACT>
__global__ __launch_bounds__(256) void k_spmm_csr(const float4* __restrict__ src,
                                                  float4* __restrict__ dst,
                                                  int loff,
                                                  const float* __restrict__ ga,
                                                  const float* __restrict__ be) {
    __shared__ float s_sc[64], s_sh[64];
    if (ACT) {
        bn_params(threadIdx.x, loff, ga, be, s_sc, s_sh);
        __syncthreads();
    }
    int warp = threadIdx.x >> 5, lane = threadIdx.x & 31;
    int half = lane >> 4, hl = lane & 15;
    int row = blockIdx.x * 16 + warp * 2 + half;
    bool valid = row < NN;
    int p  = valid ? g_rowptr[row] : 0;
    int pe = valid ? g_rowptr[row + 1] : 0;
    int len = pe - p;
    int mlen = max(len, __shfl_xor_sync(0xffffffffu, len, 16));

    float4 sc4, sh4;
    if (ACT) {
        sc4 = ((const float4*)s_sc)[hl];
        sh4 = ((const float4*)s_sh)[hl];
    }
    float4 acc = make_float4(0.f, 0.f, 0.f, 0.f);
    for (int k = 0; k < mlen; k += 4) {
#pragma unroll
        for (int j = 0; j < 4; j++) {
            int kk = k + j;
            bool on = kk < len;
            int2 e = g_csr[min(p + kk, EE - 1)];
            if (on) {
                float4 v = src[(size_t)e.x * 16 + hl];
                if (ACT) {
                    v.x = lrelu(fmaf(v.x, sc4.x, sh4.x));
                    v.y = lrelu(fmaf(v.y, sc4.y, sh4.y));
                    v.z = lrelu(fmaf(v.z, sc4.z, sh4.z));
                    v.w = lrelu(fmaf(v.w, sc4.w, sh4.w));
                }
                float w = __int_as_float(e.y);
                acc.x += w * v.x; acc.y += w * v.y;
                acc.z += w * v.z; acc.w += w * v.w;
            }
        }
    }
    if (valid) dst[(size_t)row * 16 + hl] = acc;
}

// ---------------- fused 3-matrix GEMM (f32x2) + BN-stats epilogue ----------------
// out = Z@(W0-W2) + T@W1 + P@(2*W2) + b. ACT: apply BN+lrelu to Z on load.
template <bool ACT>
__global__ __launch_bounds__(512, 1) void k_gemm3(const float* __restrict__ Z,
                                                  const float* __restrict__ T,
                                                  const float* __restrict__ P,
                                                  const float* __restrict__ W,
                                                  const float* __restrict__ bias,
                                                  float* __restrict__ out, int loff,
                                                  const float* __restrict__ ga,
                                                  const float* __restrict__ be) {
    extern __shared__ float sm[];
    float* Wd = sm;                 // 192*128 floats (splatted pairs)
    float* At = sm + 192 * 128;     // 192*128 floats
    __shared__ float s_sc[64], s_sh[64];

    int tid = threadIdx.x;
    int base = blockIdx.x * 128;

    if (ACT) bn_params(tid, loff - 64, ga, be, s_sc, s_sh);   // previous layer's stats

    for (int i = tid; i < 192 * 64; i += 512) {
        int kk = i >> 6, c = i & 63;
        int m = kk >> 6, kr = kk & 63;
        float w = W[m * 4096 + kr * 64 + c];
        if (m == 0) w -= W[8192 + kr * 64 + c];
        else if (m == 2) w *= 2.0f;
        float2* d = (float2*)(Wd + (size_t)kk * 128 + c * 2);
        *d = make_float2(w, w);
    }
    if (ACT) __syncthreads();   // s_sc/s_sh ready before Z-tile load
    const float4* srcs[3] = {(const float4*)Z, (const float4*)T, (const float4*)P};
#pragma unroll
    for (int m = 0; m < 3; m++) {
        const float4* s = srcs[m];
        for (int i = tid; i < 128 * 16; i += 512) {
            int row = i & 127, c4 = i >> 7;
            float4 v = make_float4(0.f, 0.f, 0.f, 0.f);
            if (base + row < NN) v = s[(size_t)(base + row) * 16 + c4];
            if (ACT && m == 0) {
                float4 sc4 = ((const float4*)s_sc)[c4];
                float4 sh4 = ((const float4*)s_sh)[c4];
                v.x = lrelu(fmaf(v.x, sc4.x, sh4.x));
                v.y = lrelu(fmaf(v.y, sc4.y, sh4.y));
                v.z = lrelu(fmaf(v.z, sc4.z, sh4.z));
                v.w = lrelu(fmaf(v.w, sc4.w, sh4.w));
            }
            float* d = At + (size_t)(m * 64 + c4 * 4) * 128 + row;
            d[0] = v.x; d[128] = v.y; d[256] = v.z; d[384] = v.w;
        }
    }
    __syncthreads();

    int warp = tid >> 5, lane = tid & 31;
    int j0 = warp * 4;

    u64 acc[2][4];
#pragma unroll
    for (int c = 0; c < 4; c++) {
        u64 b = splat2(bias[j0 + c]);
        acc[0][c] = b;
        acc[1][c] = b;
    }

    const char* wb = (const char*)(Wd + j0 * 2);     // + kk*512B
    const char* ab = (const char*)(At + 2 * lane);   // + kk*512B

#pragma unroll 4
    for (int kk = 0; kk < 192; kk++) {
        ulonglong2 w01 = *(const ulonglong2*)(wb + (size_t)kk * 512);
        ulonglong2 w23 = *(const ulonglong2*)(wb + (size_t)kk * 512 + 16);
        u64 a0 = *(const u64*)(ab + (size_t)kk * 512);
        u64 a1 = *(const u64*)(ab + (size_t)kk * 512 + 256);
        FMA2(acc[0][0], a0, w01.x); FMA2(acc[0][1], a0, w01.y);
        FMA2(acc[0][2], a0, w23.x); FMA2(acc[0][3], a0, w23.y);
        FMA2(acc[1][0], a1, w01.x); FMA2(acc[1][1], a1, w01.y);
        FMA2(acc[1][2], a1, w23.x); FMA2(acc[1][3], a1, w23.y);
    }

    float s[4] = {0.f, 0.f, 0.f, 0.f}, q[4] = {0.f, 0.f, 0.f, 0.f};
#pragma unroll
    for (int rp = 0; rp < 2; rp++) {
        int re = base + rp * 64 + 2 * lane;
        float lo[4], hi[4];
#pragma unroll
        for (int c = 0; c < 4; c++) unpack2(acc[rp][c], lo[c], hi[c]);
        if (re < NN) {
            *(float4*)(out + (size_t)re * 64 + j0) = make_float4(lo[0], lo[1], lo[2], lo[3]);
#pragma unroll
            for (int c = 0; c < 4; c++) { s[c] += lo[c]; q[c] += lo[c] * lo[c]; }
        }
        if (re + 1 < NN) {
            *(float4*)(out + (size_t)(re + 1) * 64 + j0) = make_float4(hi[0], hi[1], hi[2], hi[3]);
#pragma unroll
            for (int c = 0; c < 4; c++) { s[c] += hi[c]; q[c] += hi[c] * hi[c]; }
        }
    }
#pragma unroll
    for (int o = 16; o > 0; o >>= 1) {
#pragma unroll
        for (int c = 0; c < 4; c++) {
            s[c] += __shfl_down_sync(0xffffffffu, s[c], o);
            q[c] += __shfl_down_sync(0xffffffffu, q[c], o);
        }
    }
    if (lane == 0) {
#pragma unroll
        for (int c = 0; c < 4; c++) {
            atomicAdd(&g_sum[loff + j0 + c], (double)s[c]);
            atomicAdd(&g_sumsq[loff + j0 + c], (double)q[c]);
        }
    }
}

// ---------------- shortcut GEMM (f32x2): out = X @ Wsc + bsc ----------------
__global__ __launch_bounds__(512, 2) void k_sc2(const float* __restrict__ X,
                                                const float* __restrict__ W,
                                                const float* __restrict__ bias,
                                                float* __restrict__ out) {
    extern __shared__ float sm[];
    float* Wd = sm;               // 64*128
    float* At = sm + 64 * 128;    // 64*128

    int tid = threadIdx.x;
    int base = blockIdx.x * 128;

    for (int i = tid; i < 64 * 64; i += 512) {
        int kk = i >> 6, c = i & 63;
        float w = W[kk * 64 + c];
        float2* d = (float2*)(Wd + (size_t)kk * 128 + c * 2);
        *d = make_float2(w, w);
    }
    for (int i = tid; i < 128 * 16; i += 512) {
        int row = i & 127, c4 = i >> 7;
        float4 v = make_float4(0.f, 0.f, 0.f, 0.f);
        if (base + row < NN) v = ((const float4*)X)[(size_t)(base + row) * 16 + c4];
        float* d = At + (size_t)(c4 * 4) * 128 + row;
        d[0] = v.x; d[128] = v.y; d[256] = v.z; d[384] = v.w;
    }
    __syncthreads();

    int warp = tid >> 5, lane = tid & 31;
    int j0 = warp * 4;

    u64 acc[2][4];
#pragma unroll
    for (int c = 0; c < 4; c++) {
        u64 b = splat2(bias[j0 + c]);
        acc[0][c] = b;
        acc[1][c] = b;
    }
    const char* wb = (const char*)(Wd + j0 * 2);
    const char* ab = (const char*)(At + 2 * lane);
#pragma unroll 4
    for (int kk = 0; kk < 64; kk++) {
        ulonglong2 w01 = *(const ulonglong2*)(wb + (size_t)kk * 512);
        ulonglong2 w23 = *(const ulonglong2*)(wb + (size_t)kk * 512 + 16);
        u64 a0 = *(const u64*)(ab + (size_t)kk * 512);
        u64 a1 = *(const u64*)(ab + (size_t)kk * 512 + 256);
        FMA2(acc[0][0], a0, w01.x); FMA2(acc[0][1], a0, w01.y);
        FMA2(acc[0][2], a0, w23.x); FMA2(acc[0][3], a0, w23.y);
        FMA2(acc[1][0], a1, w01.x); FMA2(acc[1][1], a1, w01.y);
        FMA2(acc[1][2], a1, w23.x); FMA2(acc[1][3], a1, w23.y);
    }
#pragma unroll
    for (int rp = 0; rp < 2; rp++) {
        int re = base + rp * 64 + 2 * lane;
        float lo[4], hi[4];
#pragma unroll
        for (int c = 0; c < 4; c++) unpack2(acc[rp][c], lo[c], hi[c]);
        if (re < NN)
            *(float4*)(out + (size_t)re * 64 + j0) = make_float4(lo[0], lo[1], lo[2], lo[3]);
        if (re + 1 < NN)
            *(float4*)(out + (size_t)(re + 1) * 64 + j0) = make_float4(hi[0], hi[1], hi[2], hi[3]);
    }
}

// ---------------- layer 3: BN (inline) + lrelu + shortcut + segment-max pool ----------------
__global__ __launch_bounds__(256) void k_apply3(const float* __restrict__ pre,
                                                const float* __restrict__ sc,
                                                const int* __restrict__ batch,
                                                const float* __restrict__ ga,
                                                const float* __restrict__ be) {
    __shared__ float s_sc[64], s_sh[64];
    bn_params(threadIdx.x, 128, ga, be, s_sc, s_sh);
    __syncthreads();
    int j = threadIdx.x & 63, rg = threadIdx.x >> 6;
    int r0 = blockIdx.x * 32 + rg * 8;
    float scv = s_sc[j], shv = s_sh[j];
    float m = 0.f;
    int curb = -1;
    for (int k = 0; k < 8; k++) {
        int row = r0 + k;
        if (row >= NN) break;
        int b = batch[row];
        float v = lrelu(fmaf(pre[(size_t)row * 64 + j], scv, shv)) + sc[(size_t)row * 64 + j];
        if (b != curb) {
            if (curb >= 0) atomicMax(&g_pooled[curb * 64 + j], enc_f32(m));
            curb = b;
            m = v;
        } else {
            m = fmaxf(m, v);
        }
    }
    if (curb >= 0) atomicMax(&g_pooled[curb * 64 + j], enc_f32(m));
}

// ---------------- final: pooled @ w_lin + b_lin ----------------
__global__ void k_final(const float* __restrict__ wlin, const float* __restrict__ blin,
                        float* __restrict__ out) {
    int g = blockIdx.x, j = threadIdx.x;
    float v = dec_f32(g_pooled[g * 64 + j]) * wlin[j];
#pragma unroll
    for (int o = 16; o > 0; o >>= 1) v += __shfl_down_sync(0xffffffffu, v, o);
    __shared__ float s2[2];
    if ((j & 31) == 0) s2[j >> 5] = v;
    __syncthreads();
    if (j == 0) out[g] = s2[0] + s2[1] + blin[0];
}

// ---------------- launcher ----------------
extern "C" void kernel_launch(void* const* d_in, const int* in_sizes, int n_in,
                              void* d_out, int out_size) {
    const float* x     = (const float*)d_in[0];
    const int*   ei    = (const int*)d_in[1];
    const int*   batch = (const int*)d_in[2];
    const float* W[3]  = {(const float*)d_in[3], (const float*)d_in[5], (const float*)d_in[7]};
    const float* B[3]  = {(const float*)d_in[4], (const float*)d_in[6], (const float*)d_in[8]};
    const float* Ga[3] = {(const float*)d_in[9], (const float*)d_in[11], (const float*)d_in[13]};
    const float* Be[3] = {(const float*)d_in[10], (const float*)d_in[12], (const float*)d_in[14]};
    const float* wsc  = (const float*)d_in[15];
    const float* bsc  = (const float*)d_in[16];
    const float* wlin = (const float*)d_in[17];
    const float* blin = (const float*)d_in[18];
    float* out = (float*)d_out;

    const int GEMM_SMEM = 2 * 192 * 128 * 4;   // 196608 B
    const int SC_SMEM   = 2 * 64 * 128 * 4;    // 65536 B
    cudaFuncSetAttribute(k_gemm3<false>, cudaFuncAttributeMaxDynamicSharedMemorySize, GEMM_SMEM);
    cudaFuncSetAttribute(k_gemm3<true>,  cudaFuncAttributeMaxDynamicSharedMemorySize, GEMM_SMEM);
    cudaFuncSetAttribute(k_sc2, cudaFuncAttributeMaxDynamicSharedMemorySize, SC_SMEM);

    void *pA, *pB, *pC, *pcnt, *psum, *psumsq, *ppool;
    cudaGetSymbolAddress(&pA, g_bufA);
    cudaGetSymbolAddress(&pB, g_bufB);
    cudaGetSymbolAddress(&pC, g_bufC);
    cudaGetSymbolAddress(&pcnt, g_cnt);
    cudaGetSymbolAddress(&psum, g_sum);
    cudaGetSymbolAddress(&psumsq, g_sumsq);
    cudaGetSymbolAddress(&ppool, g_pooled);

    float* bufA = (float*)pA;
    float* bufB = (float*)pB;
    float* bufC = (float*)pC;

    const int EB = (EE + 255) / 256;
    const int NB = (NN + 255) / 256;
    const int RB = (NN + 127) / 128;           // gemm3/sc2 grid
    const int SPB = (NN + 15) / 16;            // spmm grid (16 rows/block)
    const int AB = (NN + 31) / 32;             // apply3 grid

    // ---- CSR build ----
    cudaMemsetAsync(pcnt, 0, NN * sizeof(int));
    k_deg<<<EB, 256>>>(ei);
    k_scan12<<<SCAN_B, 256>>>();
    k_scan3<<<NB, 256>>>();
    k_fill<<<EB, 256>>>(ei);

    // ---- layer 1 (no activation on input) ----
    k_spmm_csr<false><<<SPB, 256>>>((const float4*)x, (float4*)bufA, 0, nullptr, nullptr);
    k_spmm_csr<false><<<SPB, 256>>>((const float4*)bufA, (float4*)bufB, 0, nullptr, nullptr);
    cudaMemsetAsync(psum, 0, 192 * sizeof(double));
    cudaMemsetAsync(psumsq, 0, 192 * sizeof(double));
    k_gemm3<false><<<RB, 512, GEMM_SMEM>>>(x, bufA, bufB, W[0], B[0], bufC, 0, nullptr, nullptr);

    // ---- layers 2,3 (BN+lrelu fused into gather / Z-load, params inline from stats) ----
    for (int l = 1; l < 3; l++) {
        k_spmm_csr<true><<<SPB, 256>>>((const float4*)bufC, (float4*)bufA,
                                       (l - 1) * 64, Ga[l - 1], Be[l - 1]);
        k_spmm_csr<false><<<SPB, 256>>>((const float4*)bufA, (float4*)bufB, 0, nullptr, nullptr);
        k_gemm3<true><<<RB, 512, GEMM_SMEM>>>(bufC, bufA, bufB, W[l], B[l], bufC,
                                              l * 64, Ga[l - 1], Be[l - 1]);
    }

    k_sc2<<<RB, 512, SC_SMEM>>>(x, wsc, bsc, bufA);
    cudaMemsetAsync(ppool, 0, GG * 64 * sizeof(unsigned));
    k_apply3<<<AB, 256>>>(bufC, bufA, batch, Ga[2], Be[2]);
    k_final<<<GG, 64>>>(wlin, blin, out);
}